// round 10
// baseline (speedup 1.0000x reference)
#include <cuda_runtime.h>
#include <cuda_bf16.h>
#include <math.h>
#include <stdint.h>

// ---------------------------------------------------------------------------
// HydraBlock: B=4 T=2048 D=1024 H=16 HD=64 L=64 E=8   (8192 tokens)
// TF32 tensor-core GEMMs, 3-stage cp.async pipeline, 2 CTAs/SM,
// intra-tile fragment double-buffering (A) + hoisted B fragments.
// ---------------------------------------------------------------------------

#define MTOK   8192
#define DMODEL 1024
#define NHEAD  16
#define HDIM   64
#define DLAT   64
#define NEXP   8
#define EPS    1e-6f

#define STAGES 3
#define ASTR   20
#define BSTR   136
#define A_STG  (128 * ASTR)
#define B_STG  (16 * BSTR)
#define SMEM_BYTES (STAGES * (A_STG + B_STG) * 4)   // 56832

__device__ __align__(16) float g_h[MTOK * DMODEL];
__device__ __align__(16) float g_q[MTOK * DMODEL];
__device__ __align__(16) float g_dl[MTOK * DLAT];
__device__ __align__(16) float g_kv[MTOK * 2 * DMODEL];
__device__ __align__(16) float g_att[MTOK * DMODEL];
__device__ __align__(16) float g_x1[MTOK * DMODEL];
__device__ __align__(16) float g_h2[MTOK * DMODEL];
__device__ __align__(16) float g_gate[MTOK * NEXP];
__device__ __align__(16) float g_wq_t[DMODEL * DMODEL];
__device__ __align__(16) float g_wo_t[DMODEL * DMODEL];
__device__ __align__(16) float g_we_t[NEXP * DMODEL * DMODEL];

// ---------------------------------------------------------------------------
// helpers
// ---------------------------------------------------------------------------
__device__ __forceinline__ uint32_t f2tf(float x) {
    uint32_t r;
    asm("cvt.rna.tf32.f32 %0, %1;" : "=r"(r) : "f"(x));
    return r;
}
__device__ __forceinline__ float f2tff(float x) { return __uint_as_float(f2tf(x)); }

__device__ __forceinline__ void mma8(float c[4], const uint32_t a[4], const uint32_t b[2]) {
    asm volatile(
        "mma.sync.aligned.m16n8k8.row.col.f32.tf32.tf32.f32 "
        "{%0,%1,%2,%3}, {%4,%5,%6,%7}, {%8,%9}, {%0,%1,%2,%3};"
        : "+f"(c[0]), "+f"(c[1]), "+f"(c[2]), "+f"(c[3])
        : "r"(a[0]), "r"(a[1]), "r"(a[2]), "r"(a[3]), "r"(b[0]), "r"(b[1]));
}

__device__ __forceinline__ void cp16(float* dst, const float* src) {
    uint32_t d = (uint32_t)__cvta_generic_to_shared(dst);
    asm volatile("cp.async.cg.shared.global [%0], [%1], 16;" :: "r"(d), "l"(src) : "memory");
}

// fp32 -> tf32 round-half-up via integer add (mma HW truncates low 13 bits)
__device__ __forceinline__ uint32_t rnd_tf(float x) {
    return __float_as_uint(x) + 0x1000u;
}

// ---------------------------------------------------------------------------
// elementwise tf32 rounding (weights pre-pass)
// ---------------------------------------------------------------------------
__global__ void tf32_round_kernel(const float* __restrict__ in,
                                  float* __restrict__ out) {
    int i = blockIdx.x * blockDim.x + threadIdx.x;
    float4 v = ((const float4*)in)[i];
    v.x = f2tff(v.x); v.y = f2tff(v.y); v.z = f2tff(v.z); v.w = f2tff(v.w);
    ((float4*)out)[i] = v;
}

// ---------------------------------------------------------------------------
// TF32 GEMM, 3-stage cp.async pipeline, 2 CTAs/SM, fragment pipelining.
// MOE=1: K=8192 virtual; A fragment scaled by gate then re-rounded (IADD).
// ---------------------------------------------------------------------------
template <int MOE>
__global__ void __launch_bounds__(256, 2)
tf32_gemm(const float* __restrict__ A, const float* __restrict__ gate,
          const float* __restrict__ Bm, const float* __restrict__ bias,
          const float* __restrict__ Res, float* __restrict__ C,
          int M, int N, int K) {
    extern __shared__ float smem[];
    float* sA = smem;
    float* sB = smem + STAGES * A_STG;

    const int tid  = threadIdx.x;
    const int lane = tid & 31;
    const int wid  = tid >> 5;
    const int wm   = wid & 1;
    const int wn   = wid >> 1;
    const int bx   = blockIdx.x, by = blockIdx.y;

    const int astr = MOE ? DMODEL : K;

    float acc[4][4][4];
    #pragma unroll
    for (int i = 0; i < 4; i++)
        #pragma unroll
        for (int j = 0; j < 4; j++)
            #pragma unroll
            for (int r = 0; r < 4; r++) acc[i][j][r] = 0.0f;

    auto issue = [&](int kt2) {
        const int buf = kt2 % STAGES;
        const int k0  = kt2 * 16;
        const int ac  = MOE ? (k0 & (DMODEL - 1)) : k0;
        float* dA = sA + buf * A_STG;
        float* dB = sB + buf * B_STG;
        #pragma unroll
        for (int it = 0; it < 2; it++) {
            int idx = tid + it * 256;
            int r = idx >> 2, c = (idx & 3) << 2;
            cp16(dA + r * ASTR + c, A + (size_t)(by * 128 + r) * astr + ac + c);
        }
        #pragma unroll
        for (int it = 0; it < 2; it++) {
            int idx = tid + it * 256;
            int kr = idx >> 5, nc = (idx & 31) << 2;
            cp16(dB + kr * BSTR + nc, Bm + (size_t)(k0 + kr) * N + bx * 128 + nc);
        }
        asm volatile("cp.async.commit_group;" ::: "memory");
    };

    const int NT = K / 16;
    #pragma unroll
    for (int s = 0; s < STAGES - 1; s++) issue(s);

    float gr[8];
    #pragma unroll
    for (int i = 0; i < 8; i++) gr[i] = 1.0f;

    const int r0 = wm * 64 + (lane >> 2);
    const int c0 = wn * 32 + (lane >> 2);
    const int kl = lane & 3;

    for (int kt = 0; kt < NT; kt++) {
        if (MOE && (kt & 63) == 0) {
            int e = kt >> 6;
            #pragma unroll
            for (int i = 0; i < 4; i++) {
                int ra = by * 128 + r0 + i * 16;
                gr[2 * i]     = __ldg(gate + (size_t)ra * NEXP + e);
                gr[2 * i + 1] = __ldg(gate + (size_t)(ra + 8) * NEXP + e);
            }
        }
        asm volatile("cp.async.wait_group %0;" :: "n"(STAGES - 2) : "memory");
        __syncthreads();
        if (kt + STAGES - 1 < NT) issue(kt + STAGES - 1);

        const float* cA = sA + (kt % STAGES) * A_STG;
        const float* cB = sB + (kt % STAGES) * B_STG;

        // hoist ALL B fragments for both k-steps (16 regs)
        uint32_t bf[2][4][2];
        #pragma unroll
        for (int ks = 0; ks < 2; ks++) {
            const int kq = ks * 8 + kl;
            #pragma unroll
            for (int j = 0; j < 4; j++) {
                bf[ks][j][0] = __float_as_uint(cB[kq * BSTR + c0 + j * 8]);
                bf[ks][j][1] = __float_as_uint(cB[(kq + 4) * BSTR + c0 + j * 8]);
            }
        }

        // A fragments double-buffered across the 8 (ks,i) micro-steps
        uint32_t af[2][4];
        #define LDA(dst, s_) do {                                              \
            const int ks_ = (s_) >> 2, i_ = (s_) & 3;                          \
            const int kq_ = ks_ * 8 + kl;                                      \
            const int ra_ = r0 + i_ * 16;                                      \
            if (MOE) {                                                         \
                (dst)[0] = rnd_tf(cA[ra_ * ASTR + kq_] * gr[2 * i_]);          \
                (dst)[1] = rnd_tf(cA[(ra_ + 8) * ASTR + kq_] * gr[2 * i_ + 1]);\
                (dst)[2] = rnd_tf(cA[ra_ * ASTR + kq_ + 4] * gr[2 * i_]);      \
                (dst)[3] = rnd_tf(cA[(ra_ + 8) * ASTR + kq_ + 4] * gr[2 * i_ + 1]);\
            } else {                                                           \
                (dst)[0] = __float_as_uint(cA[ra_ * ASTR + kq_]);              \
                (dst)[1] = __float_as_uint(cA[(ra_ + 8) * ASTR + kq_]);        \
                (dst)[2] = __float_as_uint(cA[ra_ * ASTR + kq_ + 4]);          \
                (dst)[3] = __float_as_uint(cA[(ra_ + 8) * ASTR + kq_ + 4]);    \
            }                                                                  \
        } while (0)

        LDA(af[0], 0);
        #pragma unroll
        for (int s = 0; s < 8; s++) {
            if (s < 7) LDA(af[(s + 1) & 1], s + 1);
            const int ks = s >> 2, i = s & 3;
            #pragma unroll
            for (int j = 0; j < 4; j++)
                mma8(acc[i][j], af[s & 1], bf[ks][j]);
        }
        #undef LDA
    }

    #pragma unroll
    for (int i = 0; i < 4; i++) {
        int r = by * 128 + wm * 64 + i * 16 + (lane >> 2);
        #pragma unroll
        for (int j = 0; j < 4; j++) {
            int c = bx * 128 + wn * 32 + j * 8 + ((lane & 3) << 1);
            float bx0 = 0.0f, bx1 = 0.0f;
            if (bias) {
                float2 bb = *(const float2*)(bias + c);
                bx0 = bb.x; bx1 = bb.y;
            }
            float2 lo, hi;
            lo.x = acc[i][j][0] + bx0; lo.y = acc[i][j][1] + bx1;
            hi.x = acc[i][j][2] + bx0; hi.y = acc[i][j][3] + bx1;
            if (Res) {
                float2 r0v = *(const float2*)(Res + (size_t)r * N + c);
                float2 r1v = *(const float2*)(Res + (size_t)(r + 8) * N + c);
                lo.x += r0v.x; lo.y += r0v.y;
                hi.x += r1v.x; hi.y += r1v.y;
            }
            *(float2*)(C + (size_t)r * N + c)       = lo;
            *(float2*)(C + (size_t)(r + 8) * N + c) = hi;
        }
    }
}

// ---------------------------------------------------------------------------
// rmsnorm: output rounded to tf32
// ---------------------------------------------------------------------------
__global__ void rmsnorm_kernel(const float* __restrict__ x,
                               const float* __restrict__ gamma,
                               float* __restrict__ h) {
    int t = blockIdx.x;
    int tid = threadIdx.x;
    const float4* xr = (const float4*)(x + (size_t)t * DMODEL);
    float4 v = xr[tid];
    float ss = v.x * v.x + v.y * v.y + v.z * v.z + v.w * v.w;
    #pragma unroll
    for (int o = 16; o; o >>= 1) ss += __shfl_xor_sync(0xffffffffu, ss, o);
    __shared__ float sred[8];
    if ((tid & 31) == 0) sred[tid >> 5] = ss;
    __syncthreads();
    if (tid < 8) {
        float s = sred[tid];
        #pragma unroll
        for (int o = 4; o; o >>= 1) s += __shfl_xor_sync(0xffu, s, o);
        if (tid == 0) sred[0] = s;
    }
    __syncthreads();
    float inv = rsqrtf(sred[0] * (1.0f / DMODEL) + EPS);
    float4 g = ((const float4*)gamma)[tid];
    float4 o;
    o.x = f2tff(g.x * v.x * inv); o.y = f2tff(g.y * v.y * inv);
    o.z = f2tff(g.z * v.z * inv); o.w = f2tff(g.w * v.w * inv);
    ((float4*)(h + (size_t)t * DMODEL))[tid] = o;
}

// ---------------------------------------------------------------------------
// Tiled SGEMM (fp32 SIMT) - small GEMMs (down, kv-up)
// ---------------------------------------------------------------------------
template <int BM, int BN, int BK, int TM, int TN>
__global__ void __launch_bounds__((BM / TM) * (BN / TN))
sgemm_bias(const float* __restrict__ A,
           const float* __restrict__ Bm,
           const float* __restrict__ bias,
           const float* __restrict__ Res,
           float* __restrict__ C,
           int M, int N, int K) {
    constexpr int THREADS = (BM / TM) * (BN / TN);
    __shared__ float As[BK][BM];
    __shared__ float Bs[BK][BN];
    int bx = blockIdx.x, by = blockIdx.y;
    int tid = threadIdx.x;
    int tx = tid % (BN / TN);
    int ty = tid / (BN / TN);

    const float* Ablk = A + (size_t)by * BM * K;
    const float* Bblk = Bm + (size_t)bx * BN;

    float acc[TM][TN];
    #pragma unroll
    for (int i = 0; i < TM; i++)
        #pragma unroll
        for (int j = 0; j < TN; j++) acc[i][j] = 0.0f;

    constexpr int A_ITERS = BM * BK / (THREADS * 4);
    constexpr int B_ITERS = BK * BN / (THREADS * 4);

    for (int k0 = 0; k0 < K; k0 += BK) {
        #pragma unroll
        for (int it = 0; it < A_ITERS; ++it) {
            int idx = (tid + it * THREADS) * 4;
            int row = idx / BK, col = idx % BK;
            float4 v = *(const float4*)(Ablk + (size_t)row * K + k0 + col);
            As[col + 0][row] = v.x; As[col + 1][row] = v.y;
            As[col + 2][row] = v.z; As[col + 3][row] = v.w;
        }
        #pragma unroll
        for (int it = 0; it < B_ITERS; ++it) {
            int idx = (tid + it * THREADS) * 4;
            int row = idx / BN, col = idx % BN;
            *(float4*)(&Bs[row][col]) =
                *(const float4*)(Bblk + (size_t)(k0 + row) * N + col);
        }
        __syncthreads();
        #pragma unroll
        for (int k = 0; k < BK; k++) {
            float ar[TM], br[TN];
            #pragma unroll
            for (int i = 0; i < TM; i += 4)
                *(float4*)&ar[i] = *(float4*)&As[k][ty * TM + i];
            #pragma unroll
            for (int j = 0; j < TN; j += 4)
                *(float4*)&br[j] = *(float4*)&Bs[k][tx * TN + j];
            #pragma unroll
            for (int i = 0; i < TM; i++)
                #pragma unroll
                for (int j = 0; j < TN; j++)
                    acc[i][j] = fmaf(ar[i], br[j], acc[i][j]);
        }
        __syncthreads();
    }

    #pragma unroll
    for (int i = 0; i < TM; i++) {
        int row = by * BM + ty * TM + i;
        #pragma unroll
        for (int j = 0; j < TN; j += 4) {
            int col = bx * BN + tx * TN + j;
            float4 bsv = *(const float4*)(bias + col);
            float4 r;
            r.x = acc[i][j + 0] + bsv.x;
            r.y = acc[i][j + 1] + bsv.y;
            r.z = acc[i][j + 2] + bsv.z;
            r.w = acc[i][j + 3] + bsv.w;
            if (Res) {
                float4 rr = *(const float4*)(Res + (size_t)row * N + col);
                r.x += rr.x; r.y += rr.y; r.z += rr.z; r.w += rr.w;
            }
            *(float4*)(C + (size_t)row * N + col) = r;
        }
    }
}

// ---------------------------------------------------------------------------
// Per-token head-mixing attention; output rounded to tf32
// ---------------------------------------------------------------------------
__global__ void attn_kernel(const float* __restrict__ q,
                            const float* __restrict__ kv,
                            float* __restrict__ out) {
    int t = blockIdx.x;
    int tid = threadIdx.x;
    __shared__ float sq[DMODEL];
    __shared__ float skv[2 * DMODEL];
    __shared__ float sp[NHEAD * NHEAD];

    ((float4*)sq)[tid] = ((const float4*)(q + (size_t)t * DMODEL))[tid];
    ((float4*)skv)[tid]       = ((const float4*)(kv + (size_t)t * 2 * DMODEL))[tid];
    ((float4*)skv)[tid + 256] = ((const float4*)(kv + (size_t)t * 2 * DMODEL))[tid + 256];
    __syncthreads();

    {
        int h = tid >> 4, g = tid & 15;
        const float* qh = sq + h * HDIM;
        const float* kg = skv + g * 2 * HDIM;
        float s = 0.0f;
        #pragma unroll
        for (int d = 0; d < HDIM; d++) s = fmaf(qh[d], kg[d], s);
        sp[tid] = s * 0.125f;
    }
    __syncthreads();

    if (tid < NHEAD) {
        float mx = -1e30f;
        #pragma unroll
        for (int g = 0; g < NHEAD; g++) mx = fmaxf(mx, sp[tid * NHEAD + g]);
        float sum = 0.0f;
        #pragma unroll
        for (int g = 0; g < NHEAD; g++) {
            float e = expf(sp[tid * NHEAD + g] - mx);
            sp[tid * NHEAD + g] = e;
            sum += e;
        }
        float invs = 1.0f / sum;
        #pragma unroll
        for (int g = 0; g < NHEAD; g++) sp[tid * NHEAD + g] *= invs;
    }
    __syncthreads();

    #pragma unroll
    for (int r = 0; r < 4; r++) {
        int o = tid + r * 256;
        int h = o >> 6, dd = o & 63;
        float acc = 0.0f;
        #pragma unroll
        for (int g = 0; g < NHEAD; g++)
            acc = fmaf(sp[h * NHEAD + g], skv[g * 2 * HDIM + HDIM + dd], acc);
        out[(size_t)t * DMODEL + o] = f2tff(acc);
    }
}

// ---------------------------------------------------------------------------
// Fused rmsnorm2 + gate softmax; h2 tf32-rounded at write
// ---------------------------------------------------------------------------
__global__ void rms2_gate_kernel(const float* __restrict__ x1,
                                 const float* __restrict__ gamma,
                                 const float* __restrict__ Wg,
                                 const float* __restrict__ bg,
                                 float* __restrict__ h2,
                                 float* __restrict__ gate) {
    int t = blockIdx.x;
    int tid = threadIdx.x;
    float4 v = ((const float4*)(x1 + (size_t)t * DMODEL))[tid];
    float ss = v.x * v.x + v.y * v.y + v.z * v.z + v.w * v.w;
    #pragma unroll
    for (int o = 16; o; o >>= 1) ss += __shfl_xor_sync(0xffffffffu, ss, o);
    __shared__ float sred[8];
    __shared__ float swred[8][NEXP];
    __shared__ float slog[NEXP];
    if ((tid & 31) == 0) sred[tid >> 5] = ss;
    __syncthreads();
    if (tid < 8) {
        float s = sred[tid];
        #pragma unroll
        for (int o = 4; o; o >>= 1) s += __shfl_xor_sync(0xffu, s, o);
        if (tid == 0) sred[0] = s;
    }
    __syncthreads();
    float inv = rsqrtf(sred[0] * (1.0f / DMODEL) + EPS);
    float4 g = ((const float4*)gamma)[tid];
    float4 hv;
    hv.x = g.x * v.x * inv; hv.y = g.y * v.y * inv;
    hv.z = g.z * v.z * inv; hv.w = g.w * v.w * inv;
    float4 hr;
    hr.x = f2tff(hv.x); hr.y = f2tff(hv.y); hr.z = f2tff(hv.z); hr.w = f2tff(hv.w);
    ((float4*)(h2 + (size_t)t * DMODEL))[tid] = hr;

    int d0 = tid * 4;
    float pe[NEXP];
    #pragma unroll
    for (int e = 0; e < NEXP; e++) {
        pe[e] = hv.x * Wg[(d0 + 0) * NEXP + e]
              + hv.y * Wg[(d0 + 1) * NEXP + e]
              + hv.z * Wg[(d0 + 2) * NEXP + e]
              + hv.w * Wg[(d0 + 3) * NEXP + e];
    }
    #pragma unroll
    for (int e = 0; e < NEXP; e++)
        #pragma unroll
        for (int o = 16; o; o >>= 1)
            pe[e] += __shfl_xor_sync(0xffffffffu, pe[e], o);
    if ((tid & 31) == 0)
        #pragma unroll
        for (int e = 0; e < NEXP; e++) swred[tid >> 5][e] = pe[e];
    __syncthreads();
    if (tid < NEXP) {
        float lg = bg[tid];
        #pragma unroll
        for (int w = 0; w < 8; w++) lg += swred[w][tid];
        slog[tid] = lg;
    }
    __syncthreads();
    if (tid < NEXP) {
        float mx = slog[0];
        #pragma unroll
        for (int e = 1; e < NEXP; e++) mx = fmaxf(mx, slog[e]);
        float sum = 0.0f;
        #pragma unroll
        for (int e = 0; e < NEXP; e++) sum += expf(slog[e] - mx);
        gate[(size_t)t * NEXP + tid] = expf(slog[tid] - mx) / sum;
    }
}

// ---------------------------------------------------------------------------
// launch  (order arranged so launch #4 = tf32_gemm<0> for the ncu capture)
// ---------------------------------------------------------------------------
extern "C" void kernel_launch(void* const* d_in, const int* in_sizes, int n_in,
                              void* d_out, int out_size) {
    const float* x      = (const float*)d_in[0];
    const float* gamma1 = (const float*)d_in[1];
    const float* Wq     = (const float*)d_in[2];
    const float* bq     = (const float*)d_in[3];
    const float* Wdown  = (const float*)d_in[4];
    const float* bdown  = (const float*)d_in[5];
    const float* Wup    = (const float*)d_in[6];
    const float* bup    = (const float*)d_in[7];
    const float* Wo     = (const float*)d_in[8];
    const float* bo     = (const float*)d_in[9];
    const float* gamma2 = (const float*)d_in[10];
    const float* Wg     = (const float*)d_in[11];
    const float* bg     = (const float*)d_in[12];
    const float* We     = (const float*)d_in[13];
    float* out = (float*)d_out;

    float *h, *q, *dl, *kv, *att, *x1, *h2, *gate, *wq_t, *wo_t, *we_t;
    cudaGetSymbolAddress((void**)&h,    g_h);
    cudaGetSymbolAddress((void**)&q,    g_q);
    cudaGetSymbolAddress((void**)&dl,   g_dl);
    cudaGetSymbolAddress((void**)&kv,   g_kv);
    cudaGetSymbolAddress((void**)&att,  g_att);
    cudaGetSymbolAddress((void**)&x1,   g_x1);
    cudaGetSymbolAddress((void**)&h2,   g_h2);
    cudaGetSymbolAddress((void**)&gate, g_gate);
    cudaGetSymbolAddress((void**)&wq_t, g_wq_t);
    cudaGetSymbolAddress((void**)&wo_t, g_wo_t);
    cudaGetSymbolAddress((void**)&we_t, g_we_t);

    cudaFuncSetAttribute(tf32_gemm<0>, cudaFuncAttributeMaxDynamicSharedMemorySize, SMEM_BYTES);
    cudaFuncSetAttribute(tf32_gemm<1>, cudaFuncAttributeMaxDynamicSharedMemorySize, SMEM_BYTES);

    // 1. h = rmsnorm(x, gamma1)
    rmsnorm_kernel<<<MTOK, 256>>>(x, gamma1, h);
    // 2-3. weight rounding (Wq + We now; Wo later)
    tf32_round_kernel<<<DMODEL * DMODEL / (256 * 4), 256>>>(Wq, wq_t);
    tf32_round_kernel<<<NEXP * DMODEL * DMODEL / (256 * 4), 256>>>(We, we_t);
    // 4. q = h @ Wq + bq   <-- ncu capture slot
    {
        dim3 grid(DMODEL / 128, MTOK / 128);
        tf32_gemm<0><<<grid, 256, SMEM_BYTES>>>(h, nullptr, wq_t, bq, nullptr, q,
                                                MTOK, DMODEL, DMODEL);
    }
    // 5. dl = h @ Wdown + bdown
    {
        dim3 grid(DLAT / 64, MTOK / 64);
        sgemm_bias<64, 64, 16, 4, 4><<<grid, 256>>>(h, Wdown, bdown, nullptr, dl,
                                                    MTOK, DLAT, DMODEL);
    }
    // 6. kv = dl @ Wup + bup
    {
        dim3 grid(2 * DMODEL / 128, MTOK / 128);
        sgemm_bias<128, 128, 8, 8, 8><<<grid, 256>>>(dl, Wup, bup, nullptr, kv,
                                                     MTOK, 2 * DMODEL, DLAT);
    }
    // 7. attention
    attn_kernel<<<MTOK, 256>>>(q, kv, att);
    // 8. round Wo
    tf32_round_kernel<<<DMODEL * DMODEL / (256 * 4), 256>>>(Wo, wo_t);
    // 9. x1 = x + att @ Wo + bo
    {
        dim3 grid(DMODEL / 128, MTOK / 128);
        tf32_gemm<0><<<grid, 256, SMEM_BYTES>>>(att, nullptr, wo_t, bo, x, x1,
                                                MTOK, DMODEL, DMODEL);
    }
    // 10. h2 = rmsnorm(x1); gate = softmax(h2 @ Wg + bg)
    rms2_gate_kernel<<<MTOK, 256>>>(x1, gamma2, Wg, bg, h2, gate);
    // 11. out = x1 + MoE(h2)
    {
        dim3 grid(DMODEL / 128, MTOK / 128);
        tf32_gemm<1><<<grid, 256, SMEM_BYTES>>>(h2, gate, we_t, nullptr, x1, out,
                                                MTOK, DMODEL, NEXP * DMODEL);
    }
}

// round 14
// speedup vs baseline: 1.1591x; 1.1591x over previous
#include <cuda_runtime.h>
#include <cuda_bf16.h>
#include <math.h>
#include <stdint.h>

// ---------------------------------------------------------------------------
// HydraBlock: B=4 T=2048 D=1024 H=16 HD=64 L=64 E=8   (8192 tokens)
// TF32 legacy-mma GEMMs, K-tile=32, 2-stage cp.async pipeline, 2 CTAs/SM.
// Weights pre-rounded to tf32; activations rounded at producers.
// ---------------------------------------------------------------------------

#define MTOK   8192
#define DMODEL 1024
#define NHEAD  16
#define HDIM   64
#define DLAT   64
#define NEXP   8
#define EPS    1e-6f

#define STAGES 2
#define TCBK   32                       // K per tile
#define ASTR   36                       // A smem row stride (floats): conflict-free
#define BSTR   136                      // B smem row stride (floats): conflict-free
#define A_STG  (128 * ASTR)             // 4608 floats
#define B_STG  (TCBK * BSTR)            // 4352 floats
#define SMEM_BYTES (STAGES * (A_STG + B_STG) * 4)   // 71680

__device__ __align__(16) float g_h[MTOK * DMODEL];
__device__ __align__(16) float g_q[MTOK * DMODEL];
__device__ __align__(16) float g_dl[MTOK * DLAT];
__device__ __align__(16) float g_kv[MTOK * 2 * DMODEL];
__device__ __align__(16) float g_att[MTOK * DMODEL];
__device__ __align__(16) float g_x1[MTOK * DMODEL];
__device__ __align__(16) float g_h2[MTOK * DMODEL];
__device__ __align__(16) float g_gate[MTOK * NEXP];
__device__ __align__(16) float g_wq_t[DMODEL * DMODEL];
__device__ __align__(16) float g_wo_t[DMODEL * DMODEL];
__device__ __align__(16) float g_we_t[NEXP * DMODEL * DMODEL];

// ---------------------------------------------------------------------------
// helpers
// ---------------------------------------------------------------------------
__device__ __forceinline__ uint32_t f2tf(float x) {
    uint32_t r;
    asm("cvt.rna.tf32.f32 %0, %1;" : "=r"(r) : "f"(x));
    return r;
}
__device__ __forceinline__ float f2tff(float x) { return __uint_as_float(f2tf(x)); }

__device__ __forceinline__ void mma8(float c[4], const uint32_t a[4], const uint32_t b[2]) {
    asm volatile(
        "mma.sync.aligned.m16n8k8.row.col.f32.tf32.tf32.f32 "
        "{%0,%1,%2,%3}, {%4,%5,%6,%7}, {%8,%9}, {%0,%1,%2,%3};"
        : "+f"(c[0]), "+f"(c[1]), "+f"(c[2]), "+f"(c[3])
        : "r"(a[0]), "r"(a[1]), "r"(a[2]), "r"(a[3]), "r"(b[0]), "r"(b[1]));
}

__device__ __forceinline__ void cp16(float* dst, const float* src) {
    uint32_t d = (uint32_t)__cvta_generic_to_shared(dst);
    asm volatile("cp.async.cg.shared.global [%0], [%1], 16;" :: "r"(d), "l"(src) : "memory");
}

// fp32 -> tf32 round-half-up via integer add (mma HW truncates low 13 bits)
__device__ __forceinline__ uint32_t rnd_tf(float x) {
    return __float_as_uint(x) + 0x1000u;
}

// ---------------------------------------------------------------------------
// elementwise tf32 rounding (weights pre-pass)
// ---------------------------------------------------------------------------
__global__ void tf32_round_kernel(const float* __restrict__ in,
                                  float* __restrict__ out) {
    int i = blockIdx.x * blockDim.x + threadIdx.x;
    float4 v = ((const float4*)in)[i];
    v.x = f2tff(v.x); v.y = f2tff(v.y); v.z = f2tff(v.z); v.w = f2tff(v.w);
    ((float4*)out)[i] = v;
}

// ---------------------------------------------------------------------------
// TF32 GEMM, K-tile 32, 2-stage cp.async pipeline, 2 CTAs/SM.
// MOE=1: K=8192 virtual; A fragment scaled by gate then re-rounded (IADD).
// ---------------------------------------------------------------------------
template <int MOE>
__global__ void __launch_bounds__(256, 2)
tf32_gemm(const float* __restrict__ A, const float* __restrict__ gate,
          const float* __restrict__ Bm, const float* __restrict__ bias,
          const float* __restrict__ Res, float* __restrict__ C,
          int M, int N, int K) {
    extern __shared__ float smem[];
    float* sA = smem;
    float* sB = smem + STAGES * A_STG;

    const int tid  = threadIdx.x;
    const int lane = tid & 31;
    const int wid  = tid >> 5;
    const int wm   = wid & 1;
    const int wn   = wid >> 1;
    const int bx   = blockIdx.x, by = blockIdx.y;

    const int astr = MOE ? DMODEL : K;

    float acc[4][4][4];
    #pragma unroll
    for (int i = 0; i < 4; i++)
        #pragma unroll
        for (int j = 0; j < 4; j++)
            #pragma unroll
            for (int r = 0; r < 4; r++) acc[i][j][r] = 0.0f;

    auto issue = [&](int kt2) {
        const int buf = kt2 & 1;
        const int k0  = kt2 * TCBK;
        const int ac  = MOE ? (k0 & (DMODEL - 1)) : k0;
        float* dA = sA + buf * A_STG;
        float* dB = sB + buf * B_STG;
        // A: 128 rows x 32 k = 1024 x 16B chunks
        #pragma unroll
        for (int it = 0; it < 4; it++) {
            int idx = tid + it * 256;
            int r = idx >> 3, c = (idx & 7) << 2;
            cp16(dA + r * ASTR + c, A + (size_t)(by * 128 + r) * astr + ac + c);
        }
        // B: 32 k-rows x 128 n = 1024 x 16B chunks
        #pragma unroll
        for (int it = 0; it < 4; it++) {
            int idx = tid + it * 256;
            int kr = idx >> 5, nc = (idx & 31) << 2;
            cp16(dB + kr * BSTR + nc, Bm + (size_t)(k0 + kr) * N + bx * 128 + nc);
        }
        asm volatile("cp.async.commit_group;" ::: "memory");
    };

    const int NT = K / TCBK;
    issue(0);

    float gr[8];
    #pragma unroll
    for (int i = 0; i < 8; i++) gr[i] = 1.0f;

    const int r0 = wm * 64 + (lane >> 2);
    const int c0 = wn * 32 + (lane >> 2);
    const int kl = lane & 3;

    for (int kt = 0; kt < NT; kt++) {
        if (MOE && (kt & 31) == 0) {
            int e = kt >> 5;
            #pragma unroll
            for (int i = 0; i < 4; i++) {
                int ra = by * 128 + r0 + i * 16;
                gr[2 * i]     = __ldg(gate + (size_t)ra * NEXP + e);
                gr[2 * i + 1] = __ldg(gate + (size_t)(ra + 8) * NEXP + e);
            }
        }
        // drain current tile's copy, barrier, then prefetch next into the
        // buffer everyone has finished reading (R8-proven ordering)
        asm volatile("cp.async.wait_group 0;" ::: "memory");
        __syncthreads();
        if (kt + 1 < NT) issue(kt + 1);

        const float* cA = sA + (kt & 1) * A_STG;
        const float* cB = sB + (kt & 1) * B_STG;

        #pragma unroll
        for (int ks = 0; ks < 4; ks++) {
            const int kq = ks * 8 + kl;
            uint32_t b[4][2];
            #pragma unroll
            for (int j = 0; j < 4; j++) {
                b[j][0] = __float_as_uint(cB[kq * BSTR + c0 + j * 8]);
                b[j][1] = __float_as_uint(cB[(kq + 4) * BSTR + c0 + j * 8]);
            }
            #pragma unroll
            for (int i = 0; i < 4; i++) {
                int ra = r0 + i * 16;
                uint32_t a[4];
                if (MOE) {
                    a[0] = rnd_tf(cA[ra * ASTR + kq] * gr[2 * i]);
                    a[1] = rnd_tf(cA[(ra + 8) * ASTR + kq] * gr[2 * i + 1]);
                    a[2] = rnd_tf(cA[ra * ASTR + kq + 4] * gr[2 * i]);
                    a[3] = rnd_tf(cA[(ra + 8) * ASTR + kq + 4] * gr[2 * i + 1]);
                } else {
                    a[0] = __float_as_uint(cA[ra * ASTR + kq]);
                    a[1] = __float_as_uint(cA[(ra + 8) * ASTR + kq]);
                    a[2] = __float_as_uint(cA[ra * ASTR + kq + 4]);
                    a[3] = __float_as_uint(cA[(ra + 8) * ASTR + kq + 4]);
                }
                #pragma unroll
                for (int j = 0; j < 4; j++)
                    mma8(acc[i][j], a, b[j]);
            }
        }
    }

    #pragma unroll
    for (int i = 0; i < 4; i++) {
        int r = by * 128 + wm * 64 + i * 16 + (lane >> 2);
        #pragma unroll
        for (int j = 0; j < 4; j++) {
            int c = bx * 128 + wn * 32 + j * 8 + ((lane & 3) << 1);
            float bx0 = 0.0f, bx1 = 0.0f;
            if (bias) {
                float2 bb = *(const float2*)(bias + c);
                bx0 = bb.x; bx1 = bb.y;
            }
            float2 lo, hi;
            lo.x = acc[i][j][0] + bx0; lo.y = acc[i][j][1] + bx1;
            hi.x = acc[i][j][2] + bx0; hi.y = acc[i][j][3] + bx1;
            if (Res) {
                float2 r0v = *(const float2*)(Res + (size_t)r * N + c);
                float2 r1v = *(const float2*)(Res + (size_t)(r + 8) * N + c);
                lo.x += r0v.x; lo.y += r0v.y;
                hi.x += r1v.x; hi.y += r1v.y;
            }
            *(float2*)(C + (size_t)r * N + c)       = lo;
            *(float2*)(C + (size_t)(r + 8) * N + c) = hi;
        }
    }
}

// ---------------------------------------------------------------------------
// rmsnorm: output rounded to tf32
// ---------------------------------------------------------------------------
__global__ void rmsnorm_kernel(const float* __restrict__ x,
                               const float* __restrict__ gamma,
                               float* __restrict__ h) {
    int t = blockIdx.x;
    int tid = threadIdx.x;
    const float4* xr = (const float4*)(x + (size_t)t * DMODEL);
    float4 v = xr[tid];
    float ss = v.x * v.x + v.y * v.y + v.z * v.z + v.w * v.w;
    #pragma unroll
    for (int o = 16; o; o >>= 1) ss += __shfl_xor_sync(0xffffffffu, ss, o);
    __shared__ float sred[8];
    if ((tid & 31) == 0) sred[tid >> 5] = ss;
    __syncthreads();
    if (tid < 8) {
        float s = sred[tid];
        #pragma unroll
        for (int o = 4; o; o >>= 1) s += __shfl_xor_sync(0xffu, s, o);
        if (tid == 0) sred[0] = s;
    }
    __syncthreads();
    float inv = rsqrtf(sred[0] * (1.0f / DMODEL) + EPS);
    float4 g = ((const float4*)gamma)[tid];
    float4 o;
    o.x = f2tff(g.x * v.x * inv); o.y = f2tff(g.y * v.y * inv);
    o.z = f2tff(g.z * v.z * inv); o.w = f2tff(g.w * v.w * inv);
    ((float4*)(h + (size_t)t * DMODEL))[tid] = o;
}

// ---------------------------------------------------------------------------
// Tiled SGEMM (fp32 SIMT) - small GEMMs (down, kv-up)
// ---------------------------------------------------------------------------
template <int BM, int BN, int BK, int TM, int TN>
__global__ void __launch_bounds__((BM / TM) * (BN / TN))
sgemm_bias(const float* __restrict__ A,
           const float* __restrict__ Bm,
           const float* __restrict__ bias,
           const float* __restrict__ Res,
           float* __restrict__ C,
           int M, int N, int K) {
    constexpr int THREADS = (BM / TM) * (BN / TN);
    __shared__ float As[BK][BM];
    __shared__ float Bs[BK][BN];
    int bx = blockIdx.x, by = blockIdx.y;
    int tid = threadIdx.x;
    int tx = tid % (BN / TN);
    int ty = tid / (BN / TN);

    const float* Ablk = A + (size_t)by * BM * K;
    const float* Bblk = Bm + (size_t)bx * BN;

    float acc[TM][TN];
    #pragma unroll
    for (int i = 0; i < TM; i++)
        #pragma unroll
        for (int j = 0; j < TN; j++) acc[i][j] = 0.0f;

    constexpr int A_ITERS = BM * BK / (THREADS * 4);
    constexpr int B_ITERS = BK * BN / (THREADS * 4);

    for (int k0 = 0; k0 < K; k0 += BK) {
        #pragma unroll
        for (int it = 0; it < A_ITERS; ++it) {
            int idx = (tid + it * THREADS) * 4;
            int row = idx / BK, col = idx % BK;
            float4 v = *(const float4*)(Ablk + (size_t)row * K + k0 + col);
            As[col + 0][row] = v.x; As[col + 1][row] = v.y;
            As[col + 2][row] = v.z; As[col + 3][row] = v.w;
        }
        #pragma unroll
        for (int it = 0; it < B_ITERS; ++it) {
            int idx = (tid + it * THREADS) * 4;
            int row = idx / BN, col = idx % BN;
            *(float4*)(&Bs[row][col]) =
                *(const float4*)(Bblk + (size_t)(k0 + row) * N + col);
        }
        __syncthreads();
        #pragma unroll
        for (int k = 0; k < BK; k++) {
            float ar[TM], br[TN];
            #pragma unroll
            for (int i = 0; i < TM; i += 4)
                *(float4*)&ar[i] = *(float4*)&As[k][ty * TM + i];
            #pragma unroll
            for (int j = 0; j < TN; j += 4)
                *(float4*)&br[j] = *(float4*)&Bs[k][tx * TN + j];
            #pragma unroll
            for (int i = 0; i < TM; i++)
                #pragma unroll
                for (int j = 0; j < TN; j++)
                    acc[i][j] = fmaf(ar[i], br[j], acc[i][j]);
        }
        __syncthreads();
    }

    #pragma unroll
    for (int i = 0; i < TM; i++) {
        int row = by * BM + ty * TM + i;
        #pragma unroll
        for (int j = 0; j < TN; j += 4) {
            int col = bx * BN + tx * TN + j;
            float4 bsv = *(const float4*)(bias + col);
            float4 r;
            r.x = acc[i][j + 0] + bsv.x;
            r.y = acc[i][j + 1] + bsv.y;
            r.z = acc[i][j + 2] + bsv.z;
            r.w = acc[i][j + 3] + bsv.w;
            if (Res) {
                float4 rr = *(const float4*)(Res + (size_t)row * N + col);
                r.x += rr.x; r.y += rr.y; r.z += rr.z; r.w += rr.w;
            }
            *(float4*)(C + (size_t)row * N + col) = r;
        }
    }
}

// ---------------------------------------------------------------------------
// Per-token head-mixing attention; output rounded to tf32
// ---------------------------------------------------------------------------
__global__ void attn_kernel(const float* __restrict__ q,
                            const float* __restrict__ kv,
                            float* __restrict__ out) {
    int t = blockIdx.x;
    int tid = threadIdx.x;
    __shared__ float sq[DMODEL];
    __shared__ float skv[2 * DMODEL];
    __shared__ float sp[NHEAD * NHEAD];

    ((float4*)sq)[tid] = ((const float4*)(q + (size_t)t * DMODEL))[tid];
    ((float4*)skv)[tid]       = ((const float4*)(kv + (size_t)t * 2 * DMODEL))[tid];
    ((float4*)skv)[tid + 256] = ((const float4*)(kv + (size_t)t * 2 * DMODEL))[tid + 256];
    __syncthreads();

    {
        int h = tid >> 4, g = tid & 15;
        const float* qh = sq + h * HDIM;
        const float* kg = skv + g * 2 * HDIM;
        float s = 0.0f;
        #pragma unroll
        for (int d = 0; d < HDIM; d++) s = fmaf(qh[d], kg[d], s);
        sp[tid] = s * 0.125f;
    }
    __syncthreads();

    if (tid < NHEAD) {
        float mx = -1e30f;
        #pragma unroll
        for (int g = 0; g < NHEAD; g++) mx = fmaxf(mx, sp[tid * NHEAD + g]);
        float sum = 0.0f;
        #pragma unroll
        for (int g = 0; g < NHEAD; g++) {
            float e = expf(sp[tid * NHEAD + g] - mx);
            sp[tid * NHEAD + g] = e;
            sum += e;
        }
        float invs = 1.0f / sum;
        #pragma unroll
        for (int g = 0; g < NHEAD; g++) sp[tid * NHEAD + g] *= invs;
    }
    __syncthreads();

    #pragma unroll
    for (int r = 0; r < 4; r++) {
        int o = tid + r * 256;
        int h = o >> 6, dd = o & 63;
        float acc = 0.0f;
        #pragma unroll
        for (int g = 0; g < NHEAD; g++)
            acc = fmaf(sp[h * NHEAD + g], skv[g * 2 * HDIM + HDIM + dd], acc);
        out[(size_t)t * DMODEL + o] = f2tff(acc);
    }
}

// ---------------------------------------------------------------------------
// Fused rmsnorm2 + gate softmax; h2 tf32-rounded at write
// ---------------------------------------------------------------------------
__global__ void rms2_gate_kernel(const float* __restrict__ x1,
                                 const float* __restrict__ gamma,
                                 const float* __restrict__ Wg,
                                 const float* __restrict__ bg,
                                 float* __restrict__ h2,
                                 float* __restrict__ gate) {
    int t = blockIdx.x;
    int tid = threadIdx.x;
    float4 v = ((const float4*)(x1 + (size_t)t * DMODEL))[tid];
    float ss = v.x * v.x + v.y * v.y + v.z * v.z + v.w * v.w;
    #pragma unroll
    for (int o = 16; o; o >>= 1) ss += __shfl_xor_sync(0xffffffffu, ss, o);
    __shared__ float sred[8];
    __shared__ float swred[8][NEXP];
    __shared__ float slog[NEXP];
    if ((tid & 31) == 0) sred[tid >> 5] = ss;
    __syncthreads();
    if (tid < 8) {
        float s = sred[tid];
        #pragma unroll
        for (int o = 4; o; o >>= 1) s += __shfl_xor_sync(0xffu, s, o);
        if (tid == 0) sred[0] = s;
    }
    __syncthreads();
    float inv = rsqrtf(sred[0] * (1.0f / DMODEL) + EPS);
    float4 g = ((const float4*)gamma)[tid];
    float4 hv;
    hv.x = g.x * v.x * inv; hv.y = g.y * v.y * inv;
    hv.z = g.z * v.z * inv; hv.w = g.w * v.w * inv;
    float4 hr;
    hr.x = f2tff(hv.x); hr.y = f2tff(hv.y); hr.z = f2tff(hv.z); hr.w = f2tff(hv.w);
    ((float4*)(h2 + (size_t)t * DMODEL))[tid] = hr;

    int d0 = tid * 4;
    float pe[NEXP];
    #pragma unroll
    for (int e = 0; e < NEXP; e++) {
        pe[e] = hv.x * Wg[(d0 + 0) * NEXP + e]
              + hv.y * Wg[(d0 + 1) * NEXP + e]
              + hv.z * Wg[(d0 + 2) * NEXP + e]
              + hv.w * Wg[(d0 + 3) * NEXP + e];
    }
    #pragma unroll
    for (int e = 0; e < NEXP; e++)
        #pragma unroll
        for (int o = 16; o; o >>= 1)
            pe[e] += __shfl_xor_sync(0xffffffffu, pe[e], o);
    if ((tid & 31) == 0)
        #pragma unroll
        for (int e = 0; e < NEXP; e++) swred[tid >> 5][e] = pe[e];
    __syncthreads();
    if (tid < NEXP) {
        float lg = bg[tid];
        #pragma unroll
        for (int w = 0; w < 8; w++) lg += swred[w][tid];
        slog[tid] = lg;
    }
    __syncthreads();
    if (tid < NEXP) {
        float mx = slog[0];
        #pragma unroll
        for (int e = 1; e < NEXP; e++) mx = fmaxf(mx, slog[e]);
        float sum = 0.0f;
        #pragma unroll
        for (int e = 0; e < NEXP; e++) sum += expf(slog[e] - mx);
        gate[(size_t)t * NEXP + tid] = expf(slog[tid] - mx) / sum;
    }
}

// ---------------------------------------------------------------------------
// launch  (launch #4 = tf32_gemm<0> q-proj for the ncu capture slot)
// ---------------------------------------------------------------------------
extern "C" void kernel_launch(void* const* d_in, const int* in_sizes, int n_in,
                              void* d_out, int out_size) {
    const float* x      = (const float*)d_in[0];
    const float* gamma1 = (const float*)d_in[1];
    const float* Wq     = (const float*)d_in[2];
    const float* bq     = (const float*)d_in[3];
    const float* Wdown  = (const float*)d_in[4];
    const float* bdown  = (const float*)d_in[5];
    const float* Wup    = (const float*)d_in[6];
    const float* bup    = (const float*)d_in[7];
    const float* Wo     = (const float*)d_in[8];
    const float* bo     = (const float*)d_in[9];
    const float* gamma2 = (const float*)d_in[10];
    const float* Wg     = (const float*)d_in[11];
    const float* bg     = (const float*)d_in[12];
    const float* We     = (const float*)d_in[13];
    float* out = (float*)d_out;

    float *h, *q, *dl, *kv, *att, *x1, *h2, *gate, *wq_t, *wo_t, *we_t;
    cudaGetSymbolAddress((void**)&h,    g_h);
    cudaGetSymbolAddress((void**)&q,    g_q);
    cudaGetSymbolAddress((void**)&dl,   g_dl);
    cudaGetSymbolAddress((void**)&kv,   g_kv);
    cudaGetSymbolAddress((void**)&att,  g_att);
    cudaGetSymbolAddress((void**)&x1,   g_x1);
    cudaGetSymbolAddress((void**)&h2,   g_h2);
    cudaGetSymbolAddress((void**)&gate, g_gate);
    cudaGetSymbolAddress((void**)&wq_t, g_wq_t);
    cudaGetSymbolAddress((void**)&wo_t, g_wo_t);
    cudaGetSymbolAddress((void**)&we_t, g_we_t);

    cudaFuncSetAttribute(tf32_gemm<0>, cudaFuncAttributeMaxDynamicSharedMemorySize, SMEM_BYTES);
    cudaFuncSetAttribute(tf32_gemm<1>, cudaFuncAttributeMaxDynamicSharedMemorySize, SMEM_BYTES);

    // 1. h = rmsnorm(x, gamma1)
    rmsnorm_kernel<<<MTOK, 256>>>(x, gamma1, h);
    // 2-3. weight rounding (Wq + We now; Wo later)
    tf32_round_kernel<<<DMODEL * DMODEL / (256 * 4), 256>>>(Wq, wq_t);
    tf32_round_kernel<<<NEXP * DMODEL * DMODEL / (256 * 4), 256>>>(We, we_t);
    // 4. q = h @ Wq + bq   <-- ncu capture slot
    {
        dim3 grid(DMODEL / 128, MTOK / 128);
        tf32_gemm<0><<<grid, 256, SMEM_BYTES>>>(h, nullptr, wq_t, bq, nullptr, q,
                                                MTOK, DMODEL, DMODEL);
    }
    // 5. dl = h @ Wdown + bdown
    {
        dim3 grid(DLAT / 64, MTOK / 64);
        sgemm_bias<64, 64, 16, 4, 4><<<grid, 256>>>(h, Wdown, bdown, nullptr, dl,
                                                    MTOK, DLAT, DMODEL);
    }
    // 6. kv = dl @ Wup + bup
    {
        dim3 grid(2 * DMODEL / 128, MTOK / 128);
        sgemm_bias<128, 128, 8, 8, 8><<<grid, 256>>>(dl, Wup, bup, nullptr, kv,
                                                     MTOK, 2 * DMODEL, DLAT);
    }
    // 7. attention
    attn_kernel<<<MTOK, 256>>>(q, kv, att);
    // 8. round Wo
    tf32_round_kernel<<<DMODEL * DMODEL / (256 * 4), 256>>>(Wo, wo_t);
    // 9. x1 = x + att @ Wo + bo
    {
        dim3 grid(DMODEL / 128, MTOK / 128);
        tf32_gemm<0><<<grid, 256, SMEM_BYTES>>>(att, nullptr, wo_t, bo, x, x1,
                                                MTOK, DMODEL, DMODEL);
    }
    // 10. h2 = rmsnorm(x1); gate = softmax(h2 @ Wg + bg)
    rms2_gate_kernel<<<MTOK, 256>>>(x1, gamma2, Wg, bg, h2, gate);
    // 11. out = x1 + MoE(h2)
    {
        dim3 grid(DMODEL / 128, MTOK / 128);
        tf32_gemm<1><<<grid, 256, SMEM_BYTES>>>(h2, gate, we_t, nullptr, x1, out,
                                                MTOK, DMODEL, NEXP * DMODEL);
    }
}